// round 16
// baseline (speedup 1.0000x reference)
#include <cuda_runtime.h>
#include <cuda_bf16.h>
#include <cuda_fp16.h>
#include <math.h>
#include <stdint.h>

#define BATCH 16384
#define DIM   1024
#define DIM2  2048

// ---------------- scratch (device globals; no allocs) ----------------
__device__ __half  g_xuh[(size_t)BATCH*DIM];
__device__ __half  g_xmh[(size_t)BATCH*DIM];
__device__ __half  g_zh[(size_t)BATCH*DIM2];
__device__ __half  g_B1h[DIM*DIM], g_B2h[DIM*DIM];
__device__ __half  g_wpg[DIM*DIM2];
__device__ float   g_part[16*DIM*DIM];
__device__ float   g_c1[DIM], g_c2[DIM];
__device__ float   g_t1[DIM], g_t2[DIM], g_t3[DIM];
__device__ float2  g_rowP[BATCH];
__device__ __nv_bfloat16 g_wo1_hi[DIM*DIM], g_wo1_lo[DIM*DIM];
__device__ __nv_bfloat16 g_wvt1_hi[DIM*DIM], g_wvt1_lo[DIM*DIM];
__device__ __nv_bfloat16 g_wo2_hi[DIM*DIM], g_wo2_lo[DIM*DIM];
__device__ __nv_bfloat16 g_wvt2_hi[DIM*DIM], g_wvt2_lo[DIM*DIM];

// ---------------- low-level helpers (sm_80-baseline PTX only) ----------------
__device__ __forceinline__ uint32_t s2u(const void* p) {
    uint32_t a;
    asm("{ .reg .u64 t; cvta.to.shared.u64 t, %1; cvt.u32.u64 %0, t; }" : "=r"(a) : "l"(p));
    return a;
}
__device__ __forceinline__ void cp16(uint32_t d, const void* s) {
    asm volatile("cp.async.cg.shared.global [%0], [%1], 16;" :: "r"(d), "l"(s));
}
__device__ __forceinline__ void ldm4(uint32_t* r, uint32_t addr) {
    asm volatile("ldmatrix.sync.aligned.m8n8.x4.shared.b16 {%0,%1,%2,%3}, [%4];"
                 : "=r"(r[0]), "=r"(r[1]), "=r"(r[2]), "=r"(r[3]) : "r"(addr));
}
__device__ __forceinline__ void mma_bf16(float* d, const uint32_t* a, const uint32_t* b) {
    asm volatile(
        "mma.sync.aligned.m16n8k16.row.col.f32.bf16.bf16.f32 "
        "{%0,%1,%2,%3}, {%4,%5,%6,%7}, {%8,%9}, {%0,%1,%2,%3};"
        : "+f"(d[0]), "+f"(d[1]), "+f"(d[2]), "+f"(d[3])
        : "r"(a[0]), "r"(a[1]), "r"(a[2]), "r"(a[3]), "r"(b[0]), "r"(b[1]));
}
// fp16-accumulate variant (the rate experiment)
__device__ __forceinline__ void mma_h16(uint32_t* d, const uint32_t* a, uint32_t b0, uint32_t b1) {
    asm volatile(
        "mma.sync.aligned.m16n8k16.row.col.f16.f16.f16.f16 "
        "{%0,%1}, {%2,%3,%4,%5}, {%6,%7}, {%0,%1};"
        : "+r"(d[0]), "+r"(d[1])
        : "r"(a[0]), "r"(a[1]), "r"(a[2]), "r"(a[3]), "r"(b0), "r"(b1));
}

// ============================================================================
// fp16 GEMM core: CTA 128x128x64, 512 threads = 16 warps (4m x 4n),
// warp tile 32x32, fp16 acc promoted to fp32 every K=32, 3-stage cp.async.
// ============================================================================
#define QSTR 72
#define QA_TILE (128*QSTR*2)
#define QB_TILE (128*QSTR*2)
#define QSTAGE  (QA_TILE + QB_TILE)       // 36864 B
#define QSMEM   (3*QSTAGE)                // 110592 B

// mainloop shared by both GEMMs via macro-ish inline: implemented twice for
// distinct epilogues (z store fp16 / proj LN+GELU fp32).

#define GEMM_PROLOG(AP, BP, KDIM)                                              \
    extern __shared__ char smem[];                                             \
    const uint32_t base = s2u(smem);                                           \
    const int tid  = threadIdx.x;                                              \
    const int wid  = tid >> 5;                                                 \
    const int lane = tid & 31;                                                 \
    const int warp_m0 = (wid & 3) * 32;                                        \
    const int warp_n0 = (wid >> 2) * 32;                                       \
    float acc32[2][4][4];                                                      \
    uint32_t acc16[2][4][2];                                                   \
    _Pragma("unroll")                                                          \
    for (int i = 0; i < 2; i++)                                                \
        _Pragma("unroll")                                                      \
        for (int j = 0; j < 4; j++) {                                          \
            _Pragma("unroll")                                                  \
            for (int q = 0; q < 4; q++) acc32[i][j][q] = 0.0f;                 \
            acc16[i][j][0] = 0u; acc16[i][j][1] = 0u;                          \
        }                                                                      \
    auto load_stage = [&](int s, int k0) {                                     \
        const uint32_t stA = base + s * QSTAGE;                                \
        const uint32_t stB = stA + QA_TILE;                                    \
        for (int i = tid; i < 128 * 8; i += 512) {                             \
            const int r = i >> 3, seg = i & 7;                                 \
            cp16(stA + (uint32_t)(r * (QSTR * 2) + seg * 16),                  \
                 (AP) + (size_t)(m0 + r) * (KDIM) + k0 + seg * 8);             \
            cp16(stB + (uint32_t)(r * (QSTR * 2) + seg * 16),                  \
                 (BP) + (size_t)(n0 + r) * (KDIM) + k0 + seg * 8);             \
        }                                                                      \
        asm volatile("cp.async.commit_group;" ::: "memory");                   \
    };                                                                         \
    const int nk = (KDIM) >> 6;                                                \
    load_stage(0, 0);                                                          \
    load_stage(1, 64);                                                         \
    const int a_row = warp_m0 + (lane & 15);                                   \
    const int a_col = (lane >> 4) << 3;                                        \
    const int b_row = warp_n0 + (lane & 7) + ((lane >> 4) << 3);               \
    const int b_col = ((lane >> 3) & 1) << 3;                                  \
    for (int i = 0; i < nk; i++) {                                             \
        if (i + 2 <= nk) asm volatile("cp.async.wait_group 1;" ::: "memory");  \
        else             asm volatile("cp.async.wait_group 0;" ::: "memory");  \
        __syncthreads();                                                       \
        if (i + 2 < nk) load_stage((i + 2) % 3, (i + 2) * 64);                 \
        const uint32_t stA = base + (i % 3) * QSTAGE;                          \
        const uint32_t stB = stA + QA_TILE;                                    \
        _Pragma("unroll")                                                      \
        for (int ks = 0; ks < 4; ks++) {                                       \
            const int k0 = ks * 16;                                            \
            uint32_t af[2][4], bf[2][4];                                       \
            _Pragma("unroll")                                                  \
            for (int mf = 0; mf < 2; mf++)                                     \
                ldm4(af[mf], stA + (uint32_t)((a_row + mf * 16) * QSTR + k0 + a_col) * 2); \
            _Pragma("unroll")                                                  \
            for (int bp = 0; bp < 2; bp++)                                     \
                ldm4(bf[bp], stB + (uint32_t)((b_row + bp * 16) * QSTR + k0 + b_col) * 2); \
            _Pragma("unroll")                                                  \
            for (int mf = 0; mf < 2; mf++)                                     \
                _Pragma("unroll")                                              \
                for (int bp = 0; bp < 2; bp++) {                               \
                    mma_h16(acc16[mf][2 * bp + 0], af[mf], bf[bp][0], bf[bp][1]); \
                    mma_h16(acc16[mf][2 * bp + 1], af[mf], bf[bp][2], bf[bp][3]); \
                }                                                              \
            if (ks & 1) {                                                      \
                _Pragma("unroll")                                              \
                for (int mf = 0; mf < 2; mf++)                                 \
                    _Pragma("unroll")                                          \
                    for (int nf = 0; nf < 4; nf++) {                           \
                        float2 lo = __half22float2(*reinterpret_cast<__half2*>(&acc16[mf][nf][0])); \
                        float2 hi = __half22float2(*reinterpret_cast<__half2*>(&acc16[mf][nf][1])); \
                        acc32[mf][nf][0] += lo.x; acc32[mf][nf][1] += lo.y;    \
                        acc32[mf][nf][2] += hi.x; acc32[mf][nf][3] += hi.y;    \
                        acc16[mf][nf][0] = 0u; acc16[mf][nf][1] = 0u;          \
                    }                                                          \
            }                                                                  \
        }                                                                      \
    }

// ---- merged z-GEMM: path = blockIdx.y >> 7 ----
__global__ __launch_bounds__(512, 1)
void zgemm2(const __half* __restrict__ Axu, const __half* __restrict__ Axm,
            const __half* __restrict__ B1, const __half* __restrict__ B2,
            __half* __restrict__ Z)
{
    const int path = blockIdx.y >> 7;
    const int m0 = (blockIdx.y & 127) * 128;
    const int n0 = blockIdx.x * 128;
    const __half* A = path ? Axm : Axu;
    const __half* B = path ? B2  : B1;
    __half* C = Z + path * DIM;
    const int ldc = DIM2;

    GEMM_PROLOG(A, B, DIM)

    const int r_base = m0 + warp_m0 + (lane >> 2);
    const int c_base = n0 + warp_n0 + ((lane & 3) << 1);
#pragma unroll
    for (int mf = 0; mf < 2; mf++) {
        const int row0 = r_base + mf * 16;
#pragma unroll
        for (int nf = 0; nf < 4; nf++) {
            const int cc = c_base + nf * 8;
            *reinterpret_cast<__half2*>(C + (size_t)row0 * ldc + cc) =
                __floats2half2_rn(acc32[mf][nf][0], acc32[mf][nf][1]);
            *reinterpret_cast<__half2*>(C + (size_t)(row0 + 8) * ldc + cc) =
                __floats2half2_rn(acc32[mf][nf][2], acc32[mf][nf][3]);
        }
    }
}

// ---- proj GEMM with folded LayerNorm + exact GELU ----
__global__ __launch_bounds__(512, 1)
void proj_ln(const __half* __restrict__ A, const __half* __restrict__ B,
             float* __restrict__ C,
             const float* __restrict__ t1, const float* __restrict__ t2,
             const float* __restrict__ t3, const float2* __restrict__ rowP)
{
    const int m0 = blockIdx.y * 128;
    const int n0 = blockIdx.x * 128;
    const int ldc = DIM;

    GEMM_PROLOG(A, B, DIM2)

    const int r_base = m0 + warp_m0 + (lane >> 2);
    const int c_base = n0 + warp_n0 + ((lane & 3) << 1);
#pragma unroll
    for (int mf = 0; mf < 2; mf++) {
        const int row0 = r_base + mf * 16;
        const float2 p0 = rowP[row0];
        const float2 p1 = rowP[row0 + 8];
#pragma unroll
        for (int nf = 0; nf < 4; nf++) {
            const int cc = c_base + nf * 8;
            const float t1a = t1[cc],     t1b = t1[cc + 1];
            const float t2a = t2[cc],     t2b = t2[cc + 1];
            const float t3a = t3[cc],     t3b = t3[cc + 1];
            float v0 = p0.x * (acc32[mf][nf][0] + t3a) + t1a - p0.y * t2a;
            float v1 = p0.x * (acc32[mf][nf][1] + t3b) + t1b - p0.y * t2b;
            float v2 = p1.x * (acc32[mf][nf][2] + t3a) + t1a - p1.y * t2a;
            float v3 = p1.x * (acc32[mf][nf][3] + t3b) + t1b - p1.y * t2b;
            v0 = 0.5f * v0 * (1.0f + erff(v0 * 0.70710678118654752f));
            v1 = 0.5f * v1 * (1.0f + erff(v1 * 0.70710678118654752f));
            v2 = 0.5f * v2 * (1.0f + erff(v2 * 0.70710678118654752f));
            v3 = 0.5f * v3 * (1.0f + erff(v3 * 0.70710678118654752f));
            *reinterpret_cast<float2*>(C + (size_t)row0 * ldc + cc)       = make_float2(v0, v1);
            *reinterpret_cast<float2*>(C + (size_t)(row0 + 8) * ldc + cc) = make_float2(v2, v3);
        }
    }
}

// ============================================================================
// bf16x3 split-K GEMM, both weight combines in one launch (unchanged R15).
// ============================================================================
#define MT 256
#define NT 128
#define KC 64
#define KSLICE 128
#define STRIDE 72
#define A_TILE (MT*STRIDE*2)
#define B_TILE (NT*STRIDE*2)
#define STAGE  (2*A_TILE + 2*B_TILE)
#define SMEM_TOT (2*STAGE)

__global__ __launch_bounds__(256, 1)
void mma_gemm_sk2(const __nv_bfloat16* __restrict__ A1h, const __nv_bfloat16* __restrict__ A1l,
                  const __nv_bfloat16* __restrict__ B1hh, const __nv_bfloat16* __restrict__ B1ll,
                  const __nv_bfloat16* __restrict__ A2h, const __nv_bfloat16* __restrict__ A2l,
                  const __nv_bfloat16* __restrict__ B2hh, const __nv_bfloat16* __restrict__ B2ll,
                  float* __restrict__ Cpart)
{
    extern __shared__ char smem[];
    const uint32_t base = s2u(smem);
    const int tid  = threadIdx.x;
    const int wid  = tid >> 5;
    const int lane = tid & 31;
    const int m0 = blockIdx.y * MT;
    const int n0 = blockIdx.x * NT;
    const int path = blockIdx.z >> 3;
    const int koff = (blockIdx.z & 7) * KSLICE;
    const __nv_bfloat16* Ah = path ? A2h : A1h;
    const __nv_bfloat16* Al = path ? A2l : A1l;
    const __nv_bfloat16* Bh = path ? B2hh : B1hh;
    const __nv_bfloat16* Bl = path ? B2ll : B1ll;
    float* Cp = Cpart + (size_t)blockIdx.z * DIM * DIM;
    const int lda = DIM;
    const int warp_m0 = (wid & 3) * 64;
    const int warp_n0 = (wid >> 2) * 64;

    float acc[4][8][4];
#pragma unroll
    for (int i = 0; i < 4; i++)
#pragma unroll
        for (int j = 0; j < 8; j++)
#pragma unroll
            for (int q = 0; q < 4; q++) acc[i][j][q] = 0.0f;

    auto load_stage = [&](int s, int k0) {
        const uint32_t stA_h = base + s * STAGE;
        const uint32_t stA_l = stA_h + A_TILE;
        const uint32_t stB_h = stA_h + 2 * A_TILE;
        const uint32_t stB_l = stB_h + B_TILE;
        for (int i = tid; i < MT * 8; i += 256) {
            const int r = i >> 3, seg = i & 7;
            const uint32_t off = (uint32_t)(r * (STRIDE * 2) + seg * 16);
            const size_t gs = (size_t)(m0 + r) * lda + k0 + seg * 8;
            cp16(stA_h + off, Ah + gs);
            cp16(stA_l + off, Al + gs);
        }
        for (int i = tid; i < NT * 8; i += 256) {
            const int r = i >> 3, seg = i & 7;
            const uint32_t off = (uint32_t)(r * (STRIDE * 2) + seg * 16);
            const size_t gs = (size_t)(n0 + r) * lda + k0 + seg * 8;
            cp16(stB_h + off, Bh + gs);
            cp16(stB_l + off, Bl + gs);
        }
        asm volatile("cp.async.commit_group;" ::: "memory");
    };

    const int nk = KSLICE / KC;
    load_stage(0, koff);
    load_stage(1, koff + KC);

    const int a_row = warp_m0 + (lane & 15);
    const int a_col = (lane >> 4) << 3;
    const int b_row = warp_n0 + (lane & 7) + ((lane >> 4) << 3);
    const int b_col = ((lane >> 3) & 1) << 3;

    for (int i = 0; i < nk; i++) {
        if (i + 1 < nk) asm volatile("cp.async.wait_group 1;" ::: "memory");
        else            asm volatile("cp.async.wait_group 0;" ::: "memory");
        __syncthreads();

        const uint32_t stA_h = base + (i & 1) * STAGE;
        const uint32_t stA_l = stA_h + A_TILE;
        const uint32_t stB_h = stA_h + 2 * A_TILE;
        const uint32_t stB_l = stB_h + B_TILE;

#pragma unroll
        for (int ks = 0; ks < 4; ks++) {
            const int k0 = ks * 16;
            uint32_t ah[4][4], al[4][4], bh[4][4], bl[4][4];
#pragma unroll
            for (int mf = 0; mf < 4; mf++) {
                const uint32_t ao = (uint32_t)((a_row + mf * 16) * STRIDE + k0 + a_col) * 2;
                ldm4(ah[mf], stA_h + ao);
                ldm4(al[mf], stA_l + ao);
            }
#pragma unroll
            for (int bp = 0; bp < 4; bp++) {
                const uint32_t bo = (uint32_t)((b_row + bp * 16) * STRIDE + k0 + b_col) * 2;
                ldm4(bh[bp], stB_h + bo);
                ldm4(bl[bp], stB_l + bo);
            }
#pragma unroll
            for (int mf = 0; mf < 4; mf++)
#pragma unroll
                for (int bp = 0; bp < 4; bp++) {
                    mma_bf16(acc[mf][2 * bp + 0], ah[mf], &bh[bp][0]);
                    mma_bf16(acc[mf][2 * bp + 1], ah[mf], &bh[bp][2]);
                    mma_bf16(acc[mf][2 * bp + 0], ah[mf], &bl[bp][0]);
                    mma_bf16(acc[mf][2 * bp + 1], ah[mf], &bl[bp][2]);
                    mma_bf16(acc[mf][2 * bp + 0], al[mf], &bh[bp][0]);
                    mma_bf16(acc[mf][2 * bp + 1], al[mf], &bh[bp][2]);
                }
        }
        __syncthreads();
    }

    const int r_base = m0 + warp_m0 + (lane >> 2);
    const int c_base = n0 + warp_n0 + ((lane & 3) << 1);
#pragma unroll
    for (int mf = 0; mf < 4; mf++)
#pragma unroll
        for (int nf = 0; nf < 8; nf++) {
            const int cc = c_base + nf * 8;
            const int row0 = r_base + mf * 16;
            *reinterpret_cast<float2*>(&Cp[(size_t)row0 * DIM + cc]) =
                make_float2(acc[mf][nf][0], acc[mf][nf][1]);
            *reinterpret_cast<float2*>(&Cp[(size_t)(row0 + 8) * DIM + cc]) =
                make_float2(acc[mf][nf][2], acc[mf][nf][3]);
        }
}

// ---------------- reduce both paths' 8 partials -> fp16 B1h/B2h ----------------
__global__ void reduce8_half2(const float* __restrict__ p,
                              __half* __restrict__ o1, __half* __restrict__ o2)
{
    const int n4half = DIM * DIM / 4;
    const int total = 2 * n4half;
    const int stride = gridDim.x * blockDim.x;
    for (int i = blockIdx.x * blockDim.x + threadIdx.x; i < total; i += stride) {
        const int path = i / n4half;
        const int ii = i - path * n4half;
        const float* pb = p + (size_t)path * 8 * DIM * DIM;
        float4 s = reinterpret_cast<const float4*>(pb)[ii];
#pragma unroll
        for (int j = 1; j < 8; j++) {
            float4 v = reinterpret_cast<const float4*>(pb + (size_t)j * DIM * DIM)[ii];
            s.x += v.x; s.y += v.y; s.z += v.z; s.w += v.w;
        }
        __half* o = path ? o2 : o1;
        reinterpret_cast<__half2*>(o + (size_t)ii * 4)[0] = __floats2half2_rn(s.x, s.y);
        reinterpret_cast<__half2*>(o + (size_t)ii * 4)[1] = __floats2half2_rn(s.z, s.w);
    }
}

// ============================================================================
// fused prep kernel (coverage verified R13)
// ============================================================================
#define NCVT   4096
#define NSPL   256
#define NTSP   1024
#define NBIA   1024
#define NWPJ   512
#define PREP_GRID_1 (NCVT + NSPL + NTSP + NBIA)
#define PREP_GRID_2 (NCVT + NSPL + NTSP + NBIA + NWPJ)

__global__ __launch_bounds__(256)
void prep(const float* __restrict__ x, __half* __restrict__ xh,
          const float* __restrict__ wo,
          __nv_bfloat16* __restrict__ wo_h, __nv_bfloat16* __restrict__ wo_l,
          const float* __restrict__ wv,
          __nv_bfloat16* __restrict__ wvt_h, __nv_bfloat16* __restrict__ wvt_l,
          const float* __restrict__ bv, const float* __restrict__ bo,
          float* __restrict__ c,
          const float* __restrict__ wp, const float* __restrict__ lng,
          __half* __restrict__ wpg)
{
    const int bx = blockIdx.x;
    const int tid = threadIdx.x;

    if (bx < NCVT) {
        const int base = bx * 4096 + tid * 4;
#pragma unroll
        for (int k = 0; k < 4; k++) {
            const int idx = base + k * 1024;
            float4 v = *reinterpret_cast<const float4*>(x + idx);
            reinterpret_cast<__half2*>(xh + idx)[0] = __floats2half2_rn(v.x, v.y);
            reinterpret_cast<__half2*>(xh + idx)[1] = __floats2half2_rn(v.z, v.w);
        }
        return;
    }
    if (bx < NCVT + NSPL) {
        const int base = (bx - NCVT) * 4096 + tid * 4;
#pragma unroll
        for (int k = 0; k < 4; k++) {
            const int idx = base + k * 1024;
            float4 v = *reinterpret_cast<const float4*>(wo + idx);
            __nv_bfloat162 h0, h1, l0, l1;
            h0.x = __float2bfloat16_rn(v.x); h0.y = __float2bfloat16_rn(v.y);
            h1.x = __float2bfloat16_rn(v.z); h1.y = __float2bfloat16_rn(v.w);
            l0.x = __float2bfloat16_rn(v.x - __bfloat162float(h0.x));
            l0.y = __float2bfloat16_rn(v.y - __bfloat162float(h0.y));
            l1.x = __float2bfloat16_rn(v.z - __bfloat162float(h1.x));
            l1.y = __float2bfloat16_rn(v.w - __bfloat162float(h1.y));
            reinterpret_cast<__nv_bfloat162*>(wo_h + idx)[0] = h0;
            reinterpret_cast<__nv_bfloat162*>(wo_h + idx)[1] = h1;
            reinterpret_cast<__nv_bfloat162*>(wo_l + idx)[0] = l0;
            reinterpret_cast<__nv_bfloat162*>(wo_l + idx)[1] = l1;
        }
        return;
    }
    if (bx < NCVT + NSPL + NTSP) {
        __shared__ float t[32][33];
        const int bi = bx - NCVT - NSPL;
        const int r0 = (bi >> 5) * 32, c0 = (bi & 31) * 32;
        const int tx = tid & 31, ty = tid >> 5;
#pragma unroll
        for (int i = 0; i < 4; i++)
            t[ty + 8 * i][tx] = wv[(size_t)(r0 + ty + 8 * i) * DIM + c0 + tx];
        __syncthreads();
#pragma unroll
        for (int i = 0; i < 4; i++) {
            const int rr = ty + 8 * i;
            const float v = t[tx][rr];
            const size_t o = (size_t)(c0 + rr) * DIM + r0 + tx;
            __nv_bfloat16 hh = __float2bfloat16_rn(v);
            wvt_h[o] = hh;
            wvt_l[o] = __float2bfloat16_rn(v - __bfloat162float(hh));
        }
        return;
    }
    if (bx < NCVT + NSPL + NTSP + NBIA) {
        __shared__ float red[8];
        const int n = bx - NCVT - NSPL - NTSP;
        float s = 0.0f;
        for (int j = tid; j < DIM; j += 256) s += wo[(size_t)n * DIM + j] * bv[j];
#pragma unroll
        for (int o = 16; o > 0; o >>= 1) s += __shfl_xor_sync(0xFFFFFFFFu, s, o);
        if ((tid & 31) == 0) red[tid >> 5] = s;
        __syncthreads();
        if (tid == 0) {
            float t2 = bo[n];
#pragma unroll
            for (int w = 0; w < 8; w++) t2 += red[w];
            c[n] = t2;
        }
        return;
    }
    {
        const int base = (bx - NCVT - NSPL - NTSP - NBIA) * 4096 + tid * 4;
#pragma unroll
        for (int k = 0; k < 4; k++) {
            const int idx = base + k * 1024;
            const int kk = idx & (DIM2 - 1);
            float4 v = *reinterpret_cast<const float4*>(wp + idx);
            float4 gv = *reinterpret_cast<const float4*>(lng + kk);
            v.x *= gv.x; v.y *= gv.y; v.z *= gv.z; v.w *= gv.w;
            reinterpret_cast<__half2*>(wpg + idx)[0] = __floats2half2_rn(v.x, v.y);
            reinterpret_cast<__half2*>(wpg + idx)[1] = __floats2half2_rn(v.z, v.w);
        }
    }
}

// ---------------- t-vectors ----------------
__global__ __launch_bounds__(256)
void tvec(const float* __restrict__ wp, const float* __restrict__ g,
          const float* __restrict__ b,
          const float* __restrict__ c1, const float* __restrict__ c2,
          float* __restrict__ t1, float* __restrict__ t2, float* __restrict__ t3)
{
    __shared__ float r1[8], r2[8], r3[8];
    const int n = blockIdx.x;
    const int tid = threadIdx.x;
    float s1 = 0.0f, s2 = 0.0f, s3 = 0.0f;
    for (int j = tid * 4; j < DIM2; j += 1024) {
        float4 w  = *reinterpret_cast<const float4*>(wp + (size_t)n * DIM2 + j);
        float4 gv = *reinterpret_cast<const float4*>(g + j);
        float4 bv = *reinterpret_cast<const float4*>(b + j);
        float4 cv = (j < DIM) ? *reinterpret_cast<const float4*>(c1 + j)
                              : *reinterpret_cast<const float4*>(c2 + j - DIM);
        s1 += w.x * bv.x + w.y * bv.y + w.z * bv.z + w.w * bv.w;
        s2 += w.x * gv.x + w.y * gv.y + w.z * gv.z + w.w * gv.w;
        s3 += w.x * gv.x * cv.x + w.y * gv.y * cv.y + w.z * gv.z * cv.z + w.w * gv.w * cv.w;
    }
#pragma unroll
    for (int o = 16; o > 0; o >>= 1) {
        s1 += __shfl_xor_sync(0xFFFFFFFFu, s1, o);
        s2 += __shfl_xor_sync(0xFFFFFFFFu, s2, o);
        s3 += __shfl_xor_sync(0xFFFFFFFFu, s3, o);
    }
    if ((tid & 31) == 0) { r1[tid >> 5] = s1; r2[tid >> 5] = s2; r3[tid >> 5] = s3; }
    __syncthreads();
    if (tid == 0) {
        float a = 0, bb = 0, cc = 0;
#pragma unroll
        for (int w = 0; w < 8; w++) { a += r1[w]; bb += r2[w]; cc += r3[w]; }
        t1[n] = a; t2[n] = bb; t3[n] = cc;
    }
}

// ---------------- per-row LN stats ----------------
__global__ __launch_bounds__(256)
void stats(const __half* __restrict__ z,
           const float* __restrict__ c1, const float* __restrict__ c2,
           float2* __restrict__ rowP)
{
    __shared__ float redS[8], redQ[8];
    const size_t base = (size_t)blockIdx.x * DIM2;
    const int tid = threadIdx.x;
    const int col = tid * 8;

    uint4 zr = *reinterpret_cast<const uint4*>(z + base + col);
    float f[8];
    {
        float2 t0 = __half22float2(*reinterpret_cast<__half2*>(&zr.x));
        float2 t1 = __half22float2(*reinterpret_cast<__half2*>(&zr.y));
        float2 t2 = __half22float2(*reinterpret_cast<__half2*>(&zr.z));
        float2 t3 = __half22float2(*reinterpret_cast<__half2*>(&zr.w));
        f[0] = t0.x; f[1] = t0.y; f[2] = t1.x; f[3] = t1.y;
        f[4] = t2.x; f[5] = t2.y; f[6] = t3.x; f[7] = t3.y;
    }
    const float* cb = (col < DIM) ? (c1 + col) : (c2 + col - DIM);
    float4 cb0 = *reinterpret_cast<const float4*>(cb);
    float4 cb1 = *reinterpret_cast<const float4*>(cb + 4);
    f[0] += cb0.x; f[1] += cb0.y; f[2] += cb0.z; f[3] += cb0.w;
    f[4] += cb1.x; f[5] += cb1.y; f[6] += cb1.z; f[7] += cb1.w;

    float s = 0.0f, q = 0.0f;
#pragma unroll
    for (int i = 0; i < 8; i++) { s += f[i]; q += f[i] * f[i]; }
#pragma unroll
    for (int o = 16; o > 0; o >>= 1) {
        s += __shfl_xor_sync(0xFFFFFFFFu, s, o);
        q += __shfl_xor_sync(0xFFFFFFFFu, q, o);
    }
    if ((tid & 31) == 0) { redS[tid >> 5] = s; redQ[tid >> 5] = q; }
    __syncthreads();
    if (tid == 0) {
        float S = 0.0f, Q = 0.0f;
#pragma unroll
        for (int w = 0; w < 8; w++) { S += redS[w]; Q += redQ[w]; }
        const float mu = S * (1.0f / DIM2);
        const float var = Q * (1.0f / DIM2) - mu * mu;
        const float rstd = rsqrtf(var + 1e-5f);
        rowP[blockIdx.x] = make_float2(rstd, mu * rstd);
    }
}

// ---------------- launch ----------------
extern "C" void kernel_launch(void* const* d_in, const int* in_sizes, int n_in,
                              void* d_out, int out_size)
{
    const float* x_u    = (const float*)d_in[0];
    const float* x_m    = (const float*)d_in[1];
    const float* w_qkv1 = (const float*)d_in[2];
    const float* b_qkv1 = (const float*)d_in[3];
    const float* w_o1   = (const float*)d_in[4];
    const float* b_o1   = (const float*)d_in[5];
    const float* w_qkv2 = (const float*)d_in[6];
    const float* b_qkv2 = (const float*)d_in[7];
    const float* w_o2   = (const float*)d_in[8];
    const float* b_o2   = (const float*)d_in[9];
    const float* ln_g   = (const float*)d_in[10];
    const float* ln_b   = (const float*)d_in[11];
    const float* w_proj = (const float*)d_in[12];
    const float* b_proj = (const float*)d_in[13];
    float* out = (float*)d_out;

    const float* wv1 = w_qkv1 + (size_t)2 * DIM * DIM;
    const float* bv1 = b_qkv1 + 2 * DIM;
    const float* wv2 = w_qkv2 + (size_t)2 * DIM * DIM;
    const float* bv2 = b_qkv2 + 2 * DIM;

    __half *xuh, *xmh, *zh, *B1h, *B2h, *wpg;
    float *part, *c1, *c2, *t1, *t2, *t3;
    float2* rowP;
    __nv_bfloat16 *wo1_h, *wo1_l, *wvt1_h, *wvt1_l, *wo2_h, *wo2_l, *wvt2_h, *wvt2_l;

    cudaGetSymbolAddress((void**)&xuh, g_xuh);
    cudaGetSymbolAddress((void**)&xmh, g_xmh);
    cudaGetSymbolAddress((void**)&zh, g_zh);
    cudaGetSymbolAddress((void**)&B1h, g_B1h);
    cudaGetSymbolAddress((void**)&B2h, g_B2h);
    cudaGetSymbolAddress((void**)&wpg, g_wpg);
    cudaGetSymbolAddress((void**)&part, g_part);
    cudaGetSymbolAddress((void**)&c1, g_c1);
    cudaGetSymbolAddress((void**)&c2, g_c2);
    cudaGetSymbolAddress((void**)&t1, g_t1);
    cudaGetSymbolAddress((void**)&t2, g_t2);
    cudaGetSymbolAddress((void**)&t3, g_t3);
    cudaGetSymbolAddress((void**)&rowP, g_rowP);
    cudaGetSymbolAddress((void**)&wo1_h, g_wo1_hi);   cudaGetSymbolAddress((void**)&wo1_l, g_wo1_lo);
    cudaGetSymbolAddress((void**)&wvt1_h, g_wvt1_hi); cudaGetSymbolAddress((void**)&wvt1_l, g_wvt1_lo);
    cudaGetSymbolAddress((void**)&wo2_h, g_wo2_hi);   cudaGetSymbolAddress((void**)&wo2_l, g_wo2_lo);
    cudaGetSymbolAddress((void**)&wvt2_h, g_wvt2_hi); cudaGetSymbolAddress((void**)&wvt2_l, g_wvt2_lo);

    cudaFuncSetAttribute(mma_gemm_sk2, cudaFuncAttributeMaxDynamicSharedMemorySize, SMEM_TOT);
    cudaFuncSetAttribute(zgemm2,  cudaFuncAttributeMaxDynamicSharedMemorySize, QSMEM);
    cudaFuncSetAttribute(proj_ln, cudaFuncAttributeMaxDynamicSharedMemorySize, QSMEM);

    // 1-2) prep both paths
    prep<<<PREP_GRID_1, 256>>>(x_u, xuh, w_o1, wo1_h, wo1_l, wv1, wvt1_h, wvt1_l,
                               bv1, b_o1, c1, nullptr, nullptr, nullptr);
    prep<<<PREP_GRID_2, 256>>>(x_m, xmh, w_o2, wo2_h, wo2_l, wv2, wvt2_h, wvt2_l,
                               bv2, b_o2, c2, w_proj, ln_g, wpg);

    // 3) t-vectors
    tvec<<<DIM, 256>>>(w_proj, ln_g, ln_b, c1, c2, t1, t2, t3);

    // 4) both weight combines, split-K
    mma_gemm_sk2<<<dim3(DIM / NT, DIM / MT, 16), 256, SMEM_TOT>>>(
        wo1_h, wo1_l, wvt1_h, wvt1_l, wo2_h, wo2_l, wvt2_h, wvt2_l, part);

    // 5) reduce both -> B1h, B2h
    reduce8_half2<<<1024, 256>>>(part, B1h, B2h);

    // 6) merged z-GEMM (f16-acc experiment)
    zgemm2<<<dim3(DIM / 128, 2 * BATCH / 128), 512, QSMEM>>>(xuh, xmh, B1h, B2h, zh);

    // 7) per-row LN stats
    stats<<<BATCH, 256>>>(zh, c1, c2, rowP);

    // 8) proj GEMM with folded LN + GELU (f16-acc)
    proj_ln<<<dim3(DIM / 128, BATCH / 128), 512, QSMEM>>>(zh, wpg, out, t1, t2, t3, rowP);
}

// round 17
// speedup vs baseline: 1.4364x; 1.4364x over previous
#include <cuda_runtime.h>
#include <cuda_fp16.h>
#include <math.h>
#include <stdint.h>

#define BATCH 16384
#define DIM   1024
#define DIM2  2048

// ---------------- scratch (device globals; no allocs) ----------------
__device__ __half  g_xuh[(size_t)BATCH*DIM];
__device__ __half  g_xmh[(size_t)BATCH*DIM];
__device__ __half  g_zh[(size_t)BATCH*DIM2];
__device__ __half  g_B1h[DIM*DIM], g_B2h[DIM*DIM];
__device__ __half  g_wpg[DIM*DIM2];
__device__ float   g_part[16*DIM*DIM];
__device__ float   g_c1[DIM], g_c2[DIM];
__device__ float   g_t1[DIM], g_t2[DIM], g_t3[DIM];
__device__ float2  g_rowP[BATCH];
__device__ __half  g_wo1h[DIM*DIM], g_wvt1h[DIM*DIM];
__device__ __half  g_wo2h[DIM*DIM], g_wvt2h[DIM*DIM];

// ---------------- low-level helpers (sm_80-baseline PTX only) ----------------
__device__ __forceinline__ uint32_t s2u(const void* p) {
    uint32_t a;
    asm("{ .reg .u64 t; cvta.to.shared.u64 t, %1; cvt.u32.u64 %0, t; }" : "=r"(a) : "l"(p));
    return a;
}
__device__ __forceinline__ void cp16(uint32_t d, const void* s) {
    asm volatile("cp.async.cg.shared.global [%0], [%1], 16;" :: "r"(d), "l"(s));
}
__device__ __forceinline__ void ldm4(uint32_t* r, uint32_t addr) {
    asm volatile("ldmatrix.sync.aligned.m8n8.x4.shared.b16 {%0,%1,%2,%3}, [%4];"
                 : "=r"(r[0]), "=r"(r[1]), "=r"(r[2]), "=r"(r[3]) : "r"(addr));
}
__device__ __forceinline__ void mma_f16(float* d, const uint32_t* a, uint32_t b0, uint32_t b1) {
    asm volatile(
        "mma.sync.aligned.m16n8k16.row.col.f32.f16.f16.f32 "
        "{%0,%1,%2,%3}, {%4,%5,%6,%7}, {%8,%9}, {%0,%1,%2,%3};"
        : "+f"(d[0]), "+f"(d[1]), "+f"(d[2]), "+f"(d[3])
        : "r"(a[0]), "r"(a[1]), "r"(a[2]), "r"(a[3]), "r"(b0), "r"(b1));
}

// ============================================================================
// fp16 GEMM core config (CTA 256x128x64, 512 threads, warp tile 64x32, 3-stage)
// ============================================================================
#define HSTR 72
#define HA_TILE (256*HSTR*2)
#define HB_TILE (128*HSTR*2)
#define HSTAGE  (HA_TILE + HB_TILE)
#define HSMEM   (3*HSTAGE)

// ---- merged z-GEMM: path = blockIdx.y >> 6 ----
__global__ __launch_bounds__(512, 1)
void zgemm2(const __half* __restrict__ Axu, const __half* __restrict__ Axm,
            const __half* __restrict__ B1, const __half* __restrict__ B2,
            __half* __restrict__ Z)
{
    extern __shared__ char smem[];
    const uint32_t base = s2u(smem);
    const int tid  = threadIdx.x;
    const int wid  = tid >> 5;
    const int lane = tid & 31;
    const int path = blockIdx.y >> 6;
    const int m0 = (blockIdx.y & 63) * 256;
    const int n0 = blockIdx.x * 128;
    const __half* A = path ? Axm : Axu;
    const __half* B = path ? B2  : B1;
    __half* C = Z + path * DIM;
    const int K = DIM, ldc = DIM2;
    const int warp_m0 = (wid & 3) * 64;
    const int warp_n0 = (wid >> 2) * 32;

    float acc[4][4][4];
#pragma unroll
    for (int i = 0; i < 4; i++)
#pragma unroll
        for (int j = 0; j < 4; j++)
#pragma unroll
            for (int q = 0; q < 4; q++) acc[i][j][q] = 0.0f;

    auto load_stage = [&](int s, int k0) {
        const uint32_t stA = base + s * HSTAGE;
        const uint32_t stB = stA + HA_TILE;
        for (int i = tid; i < 256 * 8; i += 512) {
            const int r = i >> 3, seg = i & 7;
            cp16(stA + (uint32_t)(r * (HSTR * 2) + seg * 16),
                 A + (size_t)(m0 + r) * K + k0 + seg * 8);
        }
        for (int i = tid; i < 128 * 8; i += 512) {
            const int r = i >> 3, seg = i & 7;
            cp16(stB + (uint32_t)(r * (HSTR * 2) + seg * 16),
                 B + (size_t)(n0 + r) * K + k0 + seg * 8);
        }
        asm volatile("cp.async.commit_group;" ::: "memory");
    };

    const int nk = K >> 6;
    load_stage(0, 0);
    load_stage(1, 64);

    const int a_row = warp_m0 + (lane & 15);
    const int a_col = (lane >> 4) << 3;
    const int b_row = warp_n0 + (lane & 7) + ((lane >> 4) << 3);
    const int b_col = ((lane >> 3) & 1) << 3;

    for (int i = 0; i < nk; i++) {
        if (i + 2 <= nk) asm volatile("cp.async.wait_group 1;" ::: "memory");
        else             asm volatile("cp.async.wait_group 0;" ::: "memory");
        __syncthreads();
        if (i + 2 < nk) load_stage((i + 2) % 3, (i + 2) * 64);

        const uint32_t stA = base + (i % 3) * HSTAGE;
        const uint32_t stB = stA + HA_TILE;
#pragma unroll
        for (int ks = 0; ks < 4; ks++) {
            const int k0 = ks * 16;
            uint32_t af[4][4], bf[2][4];
#pragma unroll
            for (int mf = 0; mf < 4; mf++)
                ldm4(af[mf], stA + (uint32_t)((a_row + mf * 16) * HSTR + k0 + a_col) * 2);
#pragma unroll
            for (int bp = 0; bp < 2; bp++)
                ldm4(bf[bp], stB + (uint32_t)((b_row + bp * 16) * HSTR + k0 + b_col) * 2);
#pragma unroll
            for (int mf = 0; mf < 4; mf++)
#pragma unroll
                for (int bp = 0; bp < 2; bp++) {
                    mma_f16(acc[mf][2 * bp + 0], af[mf], bf[bp][0], bf[bp][1]);
                    mma_f16(acc[mf][2 * bp + 1], af[mf], bf[bp][2], bf[bp][3]);
                }
        }
    }

    const int r_base = m0 + warp_m0 + (lane >> 2);
    const int c_base = n0 + warp_n0 + ((lane & 3) << 1);
#pragma unroll
    for (int mf = 0; mf < 4; mf++) {
        const int row0 = r_base + mf * 16;
#pragma unroll
        for (int nf = 0; nf < 4; nf++) {
            const int cc = c_base + nf * 8;
            *reinterpret_cast<__half2*>(C + (size_t)row0 * ldc + cc) =
                __floats2half2_rn(acc[mf][nf][0], acc[mf][nf][1]);
            *reinterpret_cast<__half2*>(C + (size_t)(row0 + 8) * ldc + cc) =
                __floats2half2_rn(acc[mf][nf][2], acc[mf][nf][3]);
        }
    }
}

// ---- proj GEMM with folded LayerNorm + exact GELU ----
__global__ __launch_bounds__(512, 1)
void proj_ln(const __half* __restrict__ A, const __half* __restrict__ B,
             float* __restrict__ C,
             const float* __restrict__ t1, const float* __restrict__ t2,
             const float* __restrict__ t3, const float2* __restrict__ rowP)
{
    extern __shared__ char smem[];
    const uint32_t base = s2u(smem);
    const int tid  = threadIdx.x;
    const int wid  = tid >> 5;
    const int lane = tid & 31;
    const int m0 = blockIdx.y * 256;
    const int n0 = blockIdx.x * 128;
    const int K = DIM2, ldc = DIM;
    const int warp_m0 = (wid & 3) * 64;
    const int warp_n0 = (wid >> 2) * 32;

    float acc[4][4][4];
#pragma unroll
    for (int i = 0; i < 4; i++)
#pragma unroll
        for (int j = 0; j < 4; j++)
#pragma unroll
            for (int q = 0; q < 4; q++) acc[i][j][q] = 0.0f;

    auto load_stage = [&](int s, int k0) {
        const uint32_t stA = base + s * HSTAGE;
        const uint32_t stB = stA + HA_TILE;
        for (int i = tid; i < 256 * 8; i += 512) {
            const int r = i >> 3, seg = i & 7;
            cp16(stA + (uint32_t)(r * (HSTR * 2) + seg * 16),
                 A + (size_t)(m0 + r) * K + k0 + seg * 8);
        }
        for (int i = tid; i < 128 * 8; i += 512) {
            const int r = i >> 3, seg = i & 7;
            cp16(stB + (uint32_t)(r * (HSTR * 2) + seg * 16),
                 B + (size_t)(n0 + r) * K + k0 + seg * 8);
        }
        asm volatile("cp.async.commit_group;" ::: "memory");
    };

    const int nk = K >> 6;
    load_stage(0, 0);
    load_stage(1, 64);

    const int a_row = warp_m0 + (lane & 15);
    const int a_col = (lane >> 4) << 3;
    const int b_row = warp_n0 + (lane & 7) + ((lane >> 4) << 3);
    const int b_col = ((lane >> 3) & 1) << 3;

    for (int i = 0; i < nk; i++) {
        if (i + 2 <= nk) asm volatile("cp.async.wait_group 1;" ::: "memory");
        else             asm volatile("cp.async.wait_group 0;" ::: "memory");
        __syncthreads();
        if (i + 2 < nk) load_stage((i + 2) % 3, (i + 2) * 64);

        const uint32_t stA = base + (i % 3) * HSTAGE;
        const uint32_t stB = stA + HA_TILE;
#pragma unroll
        for (int ks = 0; ks < 4; ks++) {
            const int k0 = ks * 16;
            uint32_t af[4][4], bf[2][4];
#pragma unroll
            for (int mf = 0; mf < 4; mf++)
                ldm4(af[mf], stA + (uint32_t)((a_row + mf * 16) * HSTR + k0 + a_col) * 2);
#pragma unroll
            for (int bp = 0; bp < 2; bp++)
                ldm4(bf[bp], stB + (uint32_t)((b_row + bp * 16) * HSTR + k0 + b_col) * 2);
#pragma unroll
            for (int mf = 0; mf < 4; mf++)
#pragma unroll
                for (int bp = 0; bp < 2; bp++) {
                    mma_f16(acc[mf][2 * bp + 0], af[mf], bf[bp][0], bf[bp][1]);
                    mma_f16(acc[mf][2 * bp + 1], af[mf], bf[bp][2], bf[bp][3]);
                }
        }
    }

    const int r_base = m0 + warp_m0 + (lane >> 2);
    const int c_base = n0 + warp_n0 + ((lane & 3) << 1);
#pragma unroll
    for (int mf = 0; mf < 4; mf++) {
        const int row0 = r_base + mf * 16;
        const float2 p0 = rowP[row0];
        const float2 p1 = rowP[row0 + 8];
#pragma unroll
        for (int nf = 0; nf < 4; nf++) {
            const int cc = c_base + nf * 8;
            const float t1a = t1[cc],     t1b = t1[cc + 1];
            const float t2a = t2[cc],     t2b = t2[cc + 1];
            const float t3a = t3[cc],     t3b = t3[cc + 1];
            float v0 = p0.x * (acc[mf][nf][0] + t3a) + t1a - p0.y * t2a;
            float v1 = p0.x * (acc[mf][nf][1] + t3b) + t1b - p0.y * t2b;
            float v2 = p1.x * (acc[mf][nf][2] + t3a) + t1a - p1.y * t2a;
            float v3 = p1.x * (acc[mf][nf][3] + t3b) + t1b - p1.y * t2b;
            v0 = 0.5f * v0 * (1.0f + erff(v0 * 0.70710678118654752f));
            v1 = 0.5f * v1 * (1.0f + erff(v1 * 0.70710678118654752f));
            v2 = 0.5f * v2 * (1.0f + erff(v2 * 0.70710678118654752f));
            v3 = 0.5f * v3 * (1.0f + erff(v3 * 0.70710678118654752f));
            *reinterpret_cast<float2*>(C + (size_t)row0 * ldc + cc)       = make_float2(v0, v1);
            *reinterpret_cast<float2*>(C + (size_t)(row0 + 8) * ldc + cc) = make_float2(v2, v3);
        }
    }
}

// ============================================================================
// fp16 split-K combine: Cpart[z][n,k] = sum_j wo[n,j]*wvt[k,j] over K-slice.
// blockIdx.z: 0..15 = path*8 + kslice (slice of 128 in j).
// CTA tile 256x128, 256 threads, 8 warps (4m x 2n), warp tile 64x64, 2-stage.
// ============================================================================
#define CSTAGE HSTAGE
#define CSMEM  (2*CSTAGE)

__global__ __launch_bounds__(256, 1)
void combine_sk(const __half* __restrict__ A1, const __half* __restrict__ B1,
                const __half* __restrict__ A2, const __half* __restrict__ B2,
                float* __restrict__ Cpart)
{
    extern __shared__ char smem[];
    const uint32_t base = s2u(smem);
    const int tid  = threadIdx.x;
    const int wid  = tid >> 5;
    const int lane = tid & 31;
    const int m0 = blockIdx.y * 256;
    const int n0 = blockIdx.x * 128;
    const int path = blockIdx.z >> 3;
    const int koff = (blockIdx.z & 7) * 128;
    const __half* A = path ? A2 : A1;
    const __half* B = path ? B2 : B1;
    float* Cp = Cpart + (size_t)blockIdx.z * DIM * DIM;
    const int K = DIM;
    const int warp_m0 = (wid & 3) * 64;
    const int warp_n0 = (wid >> 2) * 64;

    float acc[4][8][4];
#pragma unroll
    for (int i = 0; i < 4; i++)
#pragma unroll
        for (int j = 0; j < 8; j++)
#pragma unroll
            for (int q = 0; q < 4; q++) acc[i][j][q] = 0.0f;

    auto load_stage = [&](int s, int k0) {
        const uint32_t stA = base + s * CSTAGE;
        const uint32_t stB = stA + HA_TILE;
        for (int i = tid; i < 256 * 8; i += 256) {
            const int r = i >> 3, seg = i & 7;
            cp16(stA + (uint32_t)(r * (HSTR * 2) + seg * 16),
                 A + (size_t)(m0 + r) * K + k0 + seg * 8);
        }
        for (int i = tid; i < 128 * 8; i += 256) {
            const int r = i >> 3, seg = i & 7;
            cp16(stB + (uint32_t)(r * (HSTR * 2) + seg * 16),
                 B + (size_t)(n0 + r) * K + k0 + seg * 8);
        }
        asm volatile("cp.async.commit_group;" ::: "memory");
    };

    load_stage(0, koff);
    load_stage(1, koff + 64);

    const int a_row = warp_m0 + (lane & 15);
    const int a_col = (lane >> 4) << 3;
    const int b_row = warp_n0 + (lane & 7) + ((lane >> 4) << 3);
    const int b_col = ((lane >> 3) & 1) << 3;

#pragma unroll
    for (int i = 0; i < 2; i++) {
        if (i == 0) asm volatile("cp.async.wait_group 1;" ::: "memory");
        else        asm volatile("cp.async.wait_group 0;" ::: "memory");
        __syncthreads();

        const uint32_t stA = base + i * CSTAGE;
        const uint32_t stB = stA + HA_TILE;
#pragma unroll
        for (int ks = 0; ks < 4; ks++) {
            const int k0 = ks * 16;
            uint32_t af[4][4], bf[4][4];
#pragma unroll
            for (int mf = 0; mf < 4; mf++)
                ldm4(af[mf], stA + (uint32_t)((a_row + mf * 16) * HSTR + k0 + a_col) * 2);
#pragma unroll
            for (int bp = 0; bp < 4; bp++)
                ldm4(bf[bp], stB + (uint32_t)((b_row + bp * 16) * HSTR + k0 + b_col) * 2);
#pragma unroll
            for (int mf = 0; mf < 4; mf++)
#pragma unroll
                for (int bp = 0; bp < 4; bp++) {
                    mma_f16(acc[mf][2 * bp + 0], af[mf], bf[bp][0], bf[bp][1]);
                    mma_f16(acc[mf][2 * bp + 1], af[mf], bf[bp][2], bf[bp][3]);
                }
        }
    }

    const int r_base = m0 + warp_m0 + (lane >> 2);
    const int c_base = n0 + warp_n0 + ((lane & 3) << 1);
#pragma unroll
    for (int mf = 0; mf < 4; mf++)
#pragma unroll
        for (int nf = 0; nf < 8; nf++) {
            const int cc = c_base + nf * 8;
            const int row0 = r_base + mf * 16;
            *reinterpret_cast<float2*>(&Cp[(size_t)row0 * DIM + cc]) =
                make_float2(acc[mf][nf][0], acc[mf][nf][1]);
            *reinterpret_cast<float2*>(&Cp[(size_t)(row0 + 8) * DIM + cc]) =
                make_float2(acc[mf][nf][2], acc[mf][nf][3]);
        }
}

// ---------------- reduce both paths' 8 partials -> fp16 B1h/B2h ----------------
__global__ void reduce8_half2(const float* __restrict__ p,
                              __half* __restrict__ o1, __half* __restrict__ o2)
{
    const int n4half = DIM * DIM / 4;
    const int total = 2 * n4half;
    const int stride = gridDim.x * blockDim.x;
    for (int i = blockIdx.x * blockDim.x + threadIdx.x; i < total; i += stride) {
        const int path = i / n4half;
        const int ii = i - path * n4half;
        const float* pb = p + (size_t)path * 8 * DIM * DIM;
        float4 s = reinterpret_cast<const float4*>(pb)[ii];
#pragma unroll
        for (int j = 1; j < 8; j++) {
            float4 v = reinterpret_cast<const float4*>(pb + (size_t)j * DIM * DIM)[ii];
            s.x += v.x; s.y += v.y; s.z += v.z; s.w += v.w;
        }
        __half* o = path ? o2 : o1;
        reinterpret_cast<__half2*>(o + (size_t)ii * 4)[0] = __floats2half2_rn(s.x, s.y);
        reinterpret_cast<__half2*>(o + (size_t)ii * 4)[1] = __floats2half2_rn(s.z, s.w);
    }
}

// ============================================================================
// fused prep: cvt x fp16 | cvt wo fp16 | transpose-cvt wv fp16 | biasc |
// (path2 only) wpg = g*wp fp16
// ============================================================================
#define NCVT   4096     // 4096 x 4096 floats = 16,777,216 (= x)          ✓
#define NSPL   256      // 256 x 4096 = 1,048,576 (= wo)                  ✓
#define NTSP   1024     // 32x32 tiles of 1024^2 (= wv transpose)         ✓
#define NBIA   1024
#define NWPJ   512      // 512 x 4096 = 2,097,152 (= wproj)               ✓
#define PREP_GRID_1 (NCVT + NSPL + NTSP + NBIA)
#define PREP_GRID_2 (NCVT + NSPL + NTSP + NBIA + NWPJ)

__global__ __launch_bounds__(256)
void prep(const float* __restrict__ x, __half* __restrict__ xh,
          const float* __restrict__ wo, __half* __restrict__ woh,
          const float* __restrict__ wv, __half* __restrict__ wvth,
          const float* __restrict__ bv, const float* __restrict__ bo,
          float* __restrict__ c,
          const float* __restrict__ wp, const float* __restrict__ lng,
          __half* __restrict__ wpg)
{
    const int bx = blockIdx.x;
    const int tid = threadIdx.x;

    if (bx < NCVT) {
        const int base = bx * 4096 + tid * 4;
#pragma unroll
        for (int k = 0; k < 4; k++) {
            const int idx = base + k * 1024;
            float4 v = *reinterpret_cast<const float4*>(x + idx);
            reinterpret_cast<__half2*>(xh + idx)[0] = __floats2half2_rn(v.x, v.y);
            reinterpret_cast<__half2*>(xh + idx)[1] = __floats2half2_rn(v.z, v.w);
        }
        return;
    }
    if (bx < NCVT + NSPL) {
        const int base = (bx - NCVT) * 4096 + tid * 4;
#pragma unroll
        for (int k = 0; k < 4; k++) {
            const int idx = base + k * 1024;
            float4 v = *reinterpret_cast<const float4*>(wo + idx);
            reinterpret_cast<__half2*>(woh + idx)[0] = __floats2half2_rn(v.x, v.y);
            reinterpret_cast<__half2*>(woh + idx)[1] = __floats2half2_rn(v.z, v.w);
        }
        return;
    }
    if (bx < NCVT + NSPL + NTSP) {
        __shared__ float t[32][33];
        const int bi = bx - NCVT - NSPL;
        const int r0 = (bi >> 5) * 32, c0 = (bi & 31) * 32;
        const int tx = tid & 31, ty = tid >> 5;
#pragma unroll
        for (int i = 0; i < 4; i++)
            t[ty + 8 * i][tx] = wv[(size_t)(r0 + ty + 8 * i) * DIM + c0 + tx];
        __syncthreads();
#pragma unroll
        for (int i = 0; i < 4; i++) {
            const int rr = ty + 8 * i;
            wvth[(size_t)(c0 + rr) * DIM + r0 + tx] = __float2half_rn(t[tx][rr]);
        }
        return;
    }
    if (bx < NCVT + NSPL + NTSP + NBIA) {
        __shared__ float red[8];
        const int n = bx - NCVT - NSPL - NTSP;
        float s = 0.0f;
        for (int j = tid; j < DIM; j += 256) s += wo[(size_t)n * DIM + j] * bv[j];
#pragma unroll
        for (int o = 16; o > 0; o >>= 1) s += __shfl_xor_sync(0xFFFFFFFFu, s, o);
        if ((tid & 31) == 0) red[tid >> 5] = s;
        __syncthreads();
        if (tid == 0) {
            float t2 = bo[n];
#pragma unroll
            for (int w = 0; w < 8; w++) t2 += red[w];
            c[n] = t2;
        }
        return;
    }
    {
        const int base = (bx - NCVT - NSPL - NTSP - NBIA) * 4096 + tid * 4;
#pragma unroll
        for (int k = 0; k < 4; k++) {
            const int idx = base + k * 1024;
            const int kk = idx & (DIM2 - 1);
            float4 v = *reinterpret_cast<const float4*>(wp + idx);
            float4 gv = *reinterpret_cast<const float4*>(lng + kk);
            v.x *= gv.x; v.y *= gv.y; v.z *= gv.z; v.w *= gv.w;
            reinterpret_cast<__half2*>(wpg + idx)[0] = __floats2half2_rn(v.x, v.y);
            reinterpret_cast<__half2*>(wpg + idx)[1] = __floats2half2_rn(v.z, v.w);
        }
    }
}

// ---------------- t-vectors: t1=wp·b, t2=wp·g, t3=wp·(c⊙g) ----------------
__global__ __launch_bounds__(256)
void tvec(const float* __restrict__ wp, const float* __restrict__ g,
          const float* __restrict__ b,
          const float* __restrict__ c1, const float* __restrict__ c2,
          float* __restrict__ t1, float* __restrict__ t2, float* __restrict__ t3)
{
    __shared__ float r1[8], r2[8], r3[8];
    const int n = blockIdx.x;
    const int tid = threadIdx.x;
    float s1 = 0.0f, s2 = 0.0f, s3 = 0.0f;
    for (int j = tid * 4; j < DIM2; j += 1024) {
        float4 w  = *reinterpret_cast<const float4*>(wp + (size_t)n * DIM2 + j);
        float4 gv = *reinterpret_cast<const float4*>(g + j);
        float4 bv = *reinterpret_cast<const float4*>(b + j);
        float4 cv = (j < DIM) ? *reinterpret_cast<const float4*>(c1 + j)
                              : *reinterpret_cast<const float4*>(c2 + j - DIM);
        s1 += w.x * bv.x + w.y * bv.y + w.z * bv.z + w.w * bv.w;
        s2 += w.x * gv.x + w.y * gv.y + w.z * gv.z + w.w * gv.w;
        s3 += w.x * gv.x * cv.x + w.y * gv.y * cv.y + w.z * gv.z * cv.z + w.w * gv.w * cv.w;
    }
#pragma unroll
    for (int o = 16; o > 0; o >>= 1) {
        s1 += __shfl_xor_sync(0xFFFFFFFFu, s1, o);
        s2 += __shfl_xor_sync(0xFFFFFFFFu, s2, o);
        s3 += __shfl_xor_sync(0xFFFFFFFFu, s3, o);
    }
    if ((tid & 31) == 0) { r1[tid >> 5] = s1; r2[tid >> 5] = s2; r3[tid >> 5] = s3; }
    __syncthreads();
    if (tid == 0) {
        float a = 0, bb = 0, cc = 0;
#pragma unroll
        for (int w = 0; w < 8; w++) { a += r1[w]; bb += r2[w]; cc += r3[w]; }
        t1[n] = a; t2[n] = bb; t3[n] = cc;
    }
}

// ---------------- per-row LN stats of (z + c): rowP = (rstd, mu*rstd) ----------------
__global__ __launch_bounds__(256)
void stats(const __half* __restrict__ z,
           const float* __restrict__ c1, const float* __restrict__ c2,
           float2* __restrict__ rowP)
{
    __shared__ float redS[8], redQ[8];
    const size_t base = (size_t)blockIdx.x * DIM2;
    const int tid = threadIdx.x;
    const int col = tid * 8;

    uint4 zr = *reinterpret_cast<const uint4*>(z + base + col);
    float f[8];
    {
        float2 t0 = __half22float2(*reinterpret_cast<__half2*>(&zr.x));
        float2 t1 = __half22float2(*reinterpret_cast<__half2*>(&zr.y));
        float2 t2 = __half22float2(*reinterpret_cast<__half2*>(&zr.z));
        float2 t3 = __half22float2(*reinterpret_cast<__half2*>(&zr.w));
        f[0] = t0.x; f[1] = t0.y; f[2] = t1.x; f[3] = t1.y;
        f[4] = t2.x; f[5] = t2.y; f[6] = t3.x; f[7] = t3.y;
    }
    const float* cb = (col < DIM) ? (c1 + col) : (c2 + col - DIM);
    float4 cb0 = *reinterpret_cast<const float4*>(cb);
    float4 cb1 = *reinterpret_cast<const float4*>(cb + 4);
    f[0] += cb0.x; f[1] += cb0.y; f[2] += cb0.z; f[3] += cb0.w;
    f[4] += cb1.x; f[5] += cb1.y; f[6] += cb1.z; f[7] += cb1.w;

    float s = 0.0f, q = 0.0f;
#pragma unroll
    for (int i = 0; i < 8; i++) { s += f[i]; q += f[i] * f[i]; }
#pragma unroll
    for (int o = 16; o > 0; o >>= 1) {
        s += __shfl_xor_sync(0xFFFFFFFFu, s, o);
        q += __shfl_xor_sync(0xFFFFFFFFu, q, o);
    }
    if ((tid & 31) == 0) { redS[tid >> 5] = s; redQ[tid >> 5] = q; }
    __syncthreads();
    if (tid == 0) {
        float S = 0.0f, Q = 0.0f;
#pragma unroll
        for (int w = 0; w < 8; w++) { S += redS[w]; Q += redQ[w]; }
        const float mu = S * (1.0f / DIM2);
        const float var = Q * (1.0f / DIM2) - mu * mu;
        const float rstd = rsqrtf(var + 1e-5f);
        rowP[blockIdx.x] = make_float2(rstd, mu * rstd);
    }
}

// ---------------- launch ----------------
extern "C" void kernel_launch(void* const* d_in, const int* in_sizes, int n_in,
                              void* d_out, int out_size)
{
    const float* x_u    = (const float*)d_in[0];
    const float* x_m    = (const float*)d_in[1];
    const float* w_qkv1 = (const float*)d_in[2];
    const float* b_qkv1 = (const float*)d_in[3];
    const float* w_o1   = (const float*)d_in[4];
    const float* b_o1   = (const float*)d_in[5];
    const float* w_qkv2 = (const float*)d_in[6];
    const float* b_qkv2 = (const float*)d_in[7];
    const float* w_o2   = (const float*)d_in[8];
    const float* b_o2   = (const float*)d_in[9];
    const float* ln_g   = (const float*)d_in[10];
    const float* ln_b   = (const float*)d_in[11];
    const float* w_proj = (const float*)d_in[12];
    const float* b_proj = (const float*)d_in[13];
    float* out = (float*)d_out;

    const float* wv1 = w_qkv1 + (size_t)2 * DIM * DIM;
    const float* bv1 = b_qkv1 + 2 * DIM;
    const float* wv2 = w_qkv2 + (size_t)2 * DIM * DIM;
    const float* bv2 = b_qkv2 + 2 * DIM;

    __half *xuh, *xmh, *zh, *B1h, *B2h, *wpg, *wo1h, *wvt1h, *wo2h, *wvt2h;
    float *part, *c1, *c2, *t1, *t2, *t3;
    float2* rowP;

    cudaGetSymbolAddress((void**)&xuh, g_xuh);
    cudaGetSymbolAddress((void**)&xmh, g_xmh);
    cudaGetSymbolAddress((void**)&zh, g_zh);
    cudaGetSymbolAddress((void**)&B1h, g_B1h);
    cudaGetSymbolAddress((void**)&B2h, g_B2h);
    cudaGetSymbolAddress((void**)&wpg, g_wpg);
    cudaGetSymbolAddress((void**)&part, g_part);
    cudaGetSymbolAddress((void**)&c1, g_c1);
    cudaGetSymbolAddress((void**)&c2, g_c2);
    cudaGetSymbolAddress((void**)&t1, g_t1);
    cudaGetSymbolAddress((void**)&t2, g_t2);
    cudaGetSymbolAddress((void**)&t3, g_t3);
    cudaGetSymbolAddress((void**)&rowP, g_rowP);
    cudaGetSymbolAddress((void**)&wo1h, g_wo1h);
    cudaGetSymbolAddress((void**)&wvt1h, g_wvt1h);
    cudaGetSymbolAddress((void**)&wo2h, g_wo2h);
    cudaGetSymbolAddress((void**)&wvt2h, g_wvt2h);

    cudaFuncSetAttribute(combine_sk, cudaFuncAttributeMaxDynamicSharedMemorySize, CSMEM);
    cudaFuncSetAttribute(zgemm2,  cudaFuncAttributeMaxDynamicSharedMemorySize, HSMEM);
    cudaFuncSetAttribute(proj_ln, cudaFuncAttributeMaxDynamicSharedMemorySize, HSMEM);

    // 1-2) prep both paths (fp16 converts + biasc; path2 also wpg)
    prep<<<PREP_GRID_1, 256>>>(x_u, xuh, w_o1, wo1h, wv1, wvt1h,
                               bv1, b_o1, c1, nullptr, nullptr, nullptr);
    prep<<<PREP_GRID_2, 256>>>(x_m, xmh, w_o2, wo2h, wv2, wvt2h,
                               bv2, b_o2, c2, w_proj, ln_g, wpg);

    // 3) t-vectors
    tvec<<<DIM, 256>>>(w_proj, ln_g, ln_b, c1, c2, t1, t2, t3);

    // 4) both weight combines, fp16 split-K (2 paths x 8 slices)
    combine_sk<<<dim3(DIM / 128, DIM / 256, 16), 256, CSMEM>>>(
        wo1h, wvt1h, wo2h, wvt2h, part);

    // 5) reduce both -> B1h, B2h
    reduce8_half2<<<1024, 256>>>(part, B1h, B2h);

    // 6) merged z-GEMM
    zgemm2<<<dim3(DIM / 128, 2 * BATCH / 256), 512, HSMEM>>>(xuh, xmh, B1h, B2h, zh);

    // 7) per-row LN stats
    stats<<<BATCH, 256>>>(zh, c1, c2, rowP);

    // 8) proj GEMM with folded LN + GELU
    proj_ln<<<dim3(DIM / 128, BATCH / 256), 512, HSMEM>>>(zh, wpg, out, t1, t2, t3, rowP);
}